// round 17
// baseline (speedup 1.0000x reference)
#include <cuda_runtime.h>
#include <cuda_fp16.h>
#include <math.h>
#include <stdint.h>

#define NTHREADS 512

// fp16 fragment-ordered weights in device-global scratch (L1-resident, 80 KB)
// per (nt,kp) block of 128 words; lane owns words [lane*4..lane*4+3]
#define W1H_OFF   0
#define W2H_OFF   4096
#define WRRH_OFF  8192
#define WRCH_OFF  12288
__device__ __align__(16) uint32_t g_Wf[20480];

// tanh-based GELU via MUFU.TANH
__device__ __forceinline__ float gelu_f(float x) {
    const float k0 = 0.7978845608028654f;
    const float k1 = 0.0356774081f;
    const float x2 = x * x;
    const float u  = x * fmaf(k1, x2, k0);
    float th;
    asm("tanh.approx.f32 %0, %1;" : "=f"(th) : "f"(u));
    const float hx = 0.5f * x;
    return fmaf(hx, th, hx);
}

__device__ __forceinline__ void mma16(float d[4], uint32_t a0, uint32_t a1,
                                      uint32_t a2, uint32_t a3,
                                      uint32_t b0, uint32_t b1) {
    asm volatile(
        "mma.sync.aligned.m16n8k16.row.col.f32.f16.f16.f32 "
        "{%0,%1,%2,%3}, {%4,%5,%6,%7}, {%8,%9}, {%0,%1,%2,%3};"
        : "+f"(d[0]), "+f"(d[1]), "+f"(d[2]), "+f"(d[3])
        : "r"(a0), "r"(a1), "r"(a2), "r"(a3), "r"(b0), "r"(b1));
}

__device__ __forceinline__ uint32_t pack2(float x, float y) {
    __half2 h = __floats2half2_rn(x, y);
    return *(uint32_t*)&h;
}

// one u32 word of W [K,N] row-major -> fp16 B-fragment PAIR order
__device__ __forceinline__ void pf1h(const float* __restrict__ W, int K, int N,
                                     uint32_t* __restrict__ dst, int j) {
    const int KP   = K >> 5;
    const int w    = j & 3;
    const int lane = (j >> 2) & 31;
    const int fp   = j >> 7;
    const int kp   = fp % KP;
    const int nt   = fp / KP;
    const int ks   = 2 * kp + (w >> 1);
    const int reg  = w & 1;
    const int q    = lane & 3;
    const int n    = nt * 8 + (lane >> 2);
    const int k0   = ks * 16 + 2 * q + reg * 8;
    dst[j] = pack2(W[k0 * N + n], W[(k0 + 1) * N + n]);
}

__global__ void prep_weights(const float* __restrict__ W1, const float* __restrict__ W2,
                             const float* __restrict__ Wrr, const float* __restrict__ Wrc) {
    int i = blockIdx.x * blockDim.x + threadIdx.x;
    for (; i < 20480; i += gridDim.x * blockDim.x) {
        if (i < 4096)       pf1h(W1,   64, 128, g_Wf + W1H_OFF,  i);
        else if (i < 8192)  pf1h(W2,  128,  64, g_Wf + W2H_OFF,  i - 4096);
        else if (i < 12288) pf1h(Wrr,  64, 128, g_Wf + WRRH_OFF, i - 8192);
        else                pf1h(Wrc, 128, 128, g_Wf + WRCH_OFF, i - 12288);
    }
}

__global__ void __launch_bounds__(NTHREADS, 1)
attr_rel_mma(const float* __restrict__ km,  const int* __restrict__ obsI,
             const int* __restrict__ omI,   const int* __restrict__ atI,
             const float* __restrict__ obsE, const float* __restrict__ fcorr,
             const float* __restrict__ b1,  const float* __restrict__ b2,
             const float* __restrict__ brr, const float* __restrict__ brc,
             float* __restrict__ out, int E)
{
    __shared__ float sb1[128], sb2[64], sbrr[128], sbrc[128];
    const int tid  = threadIdx.x;
    const int warp = tid >> 5;
    const int lane = tid & 31;
    const int r    = lane >> 2;
    const int q    = lane & 3;

    for (int i = tid; i < 128; i += NTHREADS) sb1[i]  = b1[i];
    for (int i = tid; i < 64;  i += NTHREADS) sb2[i]  = b2[i];
    for (int i = tid; i < 128; i += NTHREADS) sbrr[i] = brr[i];
    for (int i = tid; i < 128; i += NTHREADS) sbrc[i] = brc[i];
    __syncthreads();

    const uint32_t* W1h  = g_Wf + W1H_OFF;
    const uint32_t* W2h  = g_Wf + W2H_OFF;
    const uint32_t* Wrrh = g_Wf + WRRH_OFF;
    const uint32_t* Wrch = g_Wf + WRCH_OFF;

    const int ntiles = (E + 15) >> 4;

    // each warp owns 16 edges; fully independent (no barriers)
    for (int t = blockIdx.x * 16 + warp; t < ntiles; t += gridDim.x * 16) {
        const int base = t << 4;
        const int e0g = base + r;          // edge of this lane's row r
        const int e1g = base + r + 8;      // edge of row r+8
        const int c0 = min(e0g, E - 1);
        const int c1 = min(e1g, E - 1);

        const int j0 = atI[c0], j8 = atI[c1];
        const size_t mr0 = (size_t)omI[c0] * 64;
        const size_t mr8 = (size_t)omI[c1] * 64;
        const size_t o0  = (size_t)obsI[c0] * 128;
        const size_t o8  = (size_t)obsI[c1] * 128;

        // ---- stage 0: X = softmax(m_i*m_j) closed form, directly in A-fragment regs ----
        uint32_t X[4][4];
        {
            float v0[16], v8[16];
            float s0 = 0.f, s8 = 0.f;
            #pragma unroll
            for (int kc = 0; kc < 4; kc++)
                #pragma unroll
                for (int s = 0; s < 2; s++) {
                    const int f = kc * 16 + s * 8 + 2 * q;
                    float2 a = __ldg((const float2*)(km + mr0 + f));
                    float2 b = __ldg((const float2*)(km + mr8 + f));
                    v0[kc*4 + s*2 + 0] = a.x; v0[kc*4 + s*2 + 1] = a.y; s0 += a.x + a.y;
                    v8[kc*4 + s*2 + 0] = b.x; v8[kc*4 + s*2 + 1] = b.y; s8 += b.x + b.y;
                }
            s0 += __shfl_xor_sync(0xffffffffu, s0, 1);
            s0 += __shfl_xor_sync(0xffffffffu, s0, 2);
            s8 += __shfl_xor_sync(0xffffffffu, s8, 1);
            s8 += __shfl_xor_sync(0xffffffffu, s8, 2);
            const float mj0 = __ldg(km + mr0 + j0);
            const float mj8 = __ldg(km + mr8 + j8);
            const float kn0 = s0 - mj0;
            const float kn8 = s8 - mj8;
            const float EU = 2.71828182845904523536f;
            const float al0 = 1.f / (kn0 * EU + (64.f - kn0));
            const float be0 = EU * al0;
            const float al8 = 1.f / (kn8 * EU + (64.f - kn8));
            const float be8 = EU * al8;
            #pragma unroll
            for (int kc = 0; kc < 4; kc++) {
                const int f0 = kc * 16 + 2 * q;       // s=0 pair
                const int f1 = kc * 16 + 8 + 2 * q;   // s=1 pair
                const float x00 = (v0[kc*4+0] != 0.f && (f0)   != j0) ? be0 : al0;
                const float x01 = (v0[kc*4+1] != 0.f && (f0+1) != j0) ? be0 : al0;
                const float x80 = (v8[kc*4+0] != 0.f && (f0)   != j8) ? be8 : al8;
                const float x81 = (v8[kc*4+1] != 0.f && (f0+1) != j8) ? be8 : al8;
                const float y00 = (v0[kc*4+2] != 0.f && (f1)   != j0) ? be0 : al0;
                const float y01 = (v0[kc*4+3] != 0.f && (f1+1) != j0) ? be0 : al0;
                const float y80 = (v8[kc*4+2] != 0.f && (f1)   != j8) ? be8 : al8;
                const float y81 = (v8[kc*4+3] != 0.f && (f1+1) != j8) ? be8 : al8;
                X[kc][0] = pack2(x00, x01);
                X[kc][1] = pack2(x80, x81);
                X[kc][2] = pack2(y00, y01);
                X[kc][3] = pack2(y80, y81);
            }
        }

        // ---- stage 1: H = gelu(X @ W1 + b1)   (K=64, N=128) ----
        float acc[16][4];
        #pragma unroll
        for (int nt = 0; nt < 16; nt++)
            { acc[nt][0]=0.f; acc[nt][1]=0.f; acc[nt][2]=0.f; acc[nt][3]=0.f; }
        #pragma unroll
        for (int nt = 0; nt < 16; nt++)
            #pragma unroll
            for (int kp = 0; kp < 2; kp++) {
                const uint4 b = __ldg((const uint4*)(W1h + ((nt*2+kp)<<7) + lane*4));
                mma16(acc[nt], X[2*kp][0],   X[2*kp][1],   X[2*kp][2],   X[2*kp][3],   b.x, b.y);
                mma16(acc[nt], X[2*kp+1][0], X[2*kp+1][1], X[2*kp+1][2], X[2*kp+1][3], b.z, b.w);
            }
        uint32_t Hh[8][4];
        #pragma unroll
        for (int kc = 0; kc < 8; kc++) {
            const float2 bA = *(const float2*)(sb1 + (2*kc)*8 + 2*q);
            const float2 bB = *(const float2*)(sb1 + (2*kc+1)*8 + 2*q);
            Hh[kc][0] = pack2(gelu_f(acc[2*kc][0]+bA.x),   gelu_f(acc[2*kc][1]+bA.y));
            Hh[kc][1] = pack2(gelu_f(acc[2*kc][2]+bA.x),   gelu_f(acc[2*kc][3]+bA.y));
            Hh[kc][2] = pack2(gelu_f(acc[2*kc+1][0]+bB.x), gelu_f(acc[2*kc+1][1]+bB.y));
            Hh[kc][3] = pack2(gelu_f(acc[2*kc+1][2]+bB.x), gelu_f(acc[2*kc+1][3]+bB.y));
        }

        // ---- stage 2: T = fea_corr[j] * gelu(H @ W2 + b2)   (K=128, N=64) ----
        float ac2[8][4];
        #pragma unroll
        for (int nt = 0; nt < 8; nt++)
            { ac2[nt][0]=0.f; ac2[nt][1]=0.f; ac2[nt][2]=0.f; ac2[nt][3]=0.f; }
        #pragma unroll
        for (int nt = 0; nt < 8; nt++)
            #pragma unroll
            for (int kp = 0; kp < 4; kp++) {
                const uint4 b = __ldg((const uint4*)(W2h + ((nt*4+kp)<<7) + lane*4));
                mma16(ac2[nt], Hh[2*kp][0],   Hh[2*kp][1],   Hh[2*kp][2],   Hh[2*kp][3],   b.x, b.y);
                mma16(ac2[nt], Hh[2*kp+1][0], Hh[2*kp+1][1], Hh[2*kp+1][2], Hh[2*kp+1][3], b.z, b.w);
            }
        uint32_t Th[4][4];
        #pragma unroll
        for (int kc = 0; kc < 4; kc++) {
            const int nA = (2*kc)*8 + 2*q, nB = (2*kc+1)*8 + 2*q;
            const float2 bA = *(const float2*)(sb2 + nA);
            const float2 bB = *(const float2*)(sb2 + nB);
            const float2 fA0 = __ldg((const float2*)(fcorr + (size_t)j0*64 + nA));
            const float2 fA8 = __ldg((const float2*)(fcorr + (size_t)j8*64 + nA));
            const float2 fB0 = __ldg((const float2*)(fcorr + (size_t)j0*64 + nB));
            const float2 fB8 = __ldg((const float2*)(fcorr + (size_t)j8*64 + nB));
            Th[kc][0] = pack2(fA0.x*gelu_f(ac2[2*kc][0]+bA.x),   fA0.y*gelu_f(ac2[2*kc][1]+bA.y));
            Th[kc][1] = pack2(fA8.x*gelu_f(ac2[2*kc][2]+bA.x),   fA8.y*gelu_f(ac2[2*kc][3]+bA.y));
            Th[kc][2] = pack2(fB0.x*gelu_f(ac2[2*kc+1][0]+bB.x), fB0.y*gelu_f(ac2[2*kc+1][1]+bB.y));
            Th[kc][3] = pack2(fB8.x*gelu_f(ac2[2*kc+1][2]+bB.x), fB8.y*gelu_f(ac2[2*kc+1][3]+bB.y));
        }

        // ---- stage 3: U = obs_h * gelu(T @ Wrr + brr)   (K=64, N=128) ----
        #pragma unroll
        for (int nt = 0; nt < 16; nt++)
            { acc[nt][0]=0.f; acc[nt][1]=0.f; acc[nt][2]=0.f; acc[nt][3]=0.f; }
        #pragma unroll
        for (int nt = 0; nt < 16; nt++)
            #pragma unroll
            for (int kp = 0; kp < 2; kp++) {
                const uint4 b = __ldg((const uint4*)(Wrrh + ((nt*2+kp)<<7) + lane*4));
                mma16(acc[nt], Th[2*kp][0],   Th[2*kp][1],   Th[2*kp][2],   Th[2*kp][3],   b.x, b.y);
                mma16(acc[nt], Th[2*kp+1][0], Th[2*kp+1][1], Th[2*kp+1][2], Th[2*kp+1][3], b.z, b.w);
            }
        uint32_t Uh[8][4];
        #pragma unroll
        for (int kc = 0; kc < 8; kc++) {
            const int nA = (2*kc)*8 + 2*q, nB = (2*kc+1)*8 + 2*q;
            const float2 bA = *(const float2*)(sbrr + nA);
            const float2 bB = *(const float2*)(sbrr + nB);
            const float2 vA0 = __ldg((const float2*)(obsE + o0 + nA));
            const float2 vA8 = __ldg((const float2*)(obsE + o8 + nA));
            const float2 vB0 = __ldg((const float2*)(obsE + o0 + nB));
            const float2 vB8 = __ldg((const float2*)(obsE + o8 + nB));
            Uh[kc][0] = pack2(vA0.x*gelu_f(acc[2*kc][0]+bA.x),   vA0.y*gelu_f(acc[2*kc][1]+bA.y));
            Uh[kc][1] = pack2(vA8.x*gelu_f(acc[2*kc][2]+bA.x),   vA8.y*gelu_f(acc[2*kc][3]+bA.y));
            Uh[kc][2] = pack2(vB0.x*gelu_f(acc[2*kc+1][0]+bB.x), vB0.y*gelu_f(acc[2*kc+1][1]+bB.y));
            Uh[kc][3] = pack2(vB8.x*gelu_f(acc[2*kc+1][2]+bB.x), vB8.y*gelu_f(acc[2*kc+1][3]+bB.y));
        }

        // ---- stage 4: out = gelu(U @ Wrc + brc)   (K=128, N=128) ----
        #pragma unroll
        for (int nt = 0; nt < 16; nt++)
            { acc[nt][0]=0.f; acc[nt][1]=0.f; acc[nt][2]=0.f; acc[nt][3]=0.f; }
        #pragma unroll
        for (int nt = 0; nt < 16; nt++)
            #pragma unroll
            for (int kp = 0; kp < 4; kp++) {
                const uint4 b = __ldg((const uint4*)(Wrch + ((nt*4+kp)<<7) + lane*4));
                mma16(acc[nt], Uh[2*kp][0],   Uh[2*kp][1],   Uh[2*kp][2],   Uh[2*kp][3],   b.x, b.y);
                mma16(acc[nt], Uh[2*kp+1][0], Uh[2*kp+1][1], Uh[2*kp+1][2], Uh[2*kp+1][3], b.z, b.w);
            }
        const bool p0 = e0g < E, p1 = e1g < E;
        float* po0 = out + (size_t)e0g * 128;
        float* po1 = out + (size_t)e1g * 128;
        #pragma unroll
        for (int nt = 0; nt < 16; nt++) {
            const int n0 = nt * 8 + 2 * q;
            const float2 bb = *(const float2*)(sbrc + n0);
            if (p0) {
                float2 v;
                v.x = gelu_f(acc[nt][0] + bb.x);
                v.y = gelu_f(acc[nt][1] + bb.y);
                *(float2*)(po0 + n0) = v;
            }
            if (p1) {
                float2 v;
                v.x = gelu_f(acc[nt][2] + bb.x);
                v.y = gelu_f(acc[nt][3] + bb.y);
                *(float2*)(po1 + n0) = v;
            }
        }
    }
}

extern "C" void kernel_launch(void* const* d_in, const int* in_sizes, int n_in,
                              void* d_out, int out_size) {
    const float* known_mask   = (const float*)d_in[0];
    const int*   obs_idx      = (const int*)  d_in[1];
    const int*   obs_mask_idx = (const int*)  d_in[2];
    const int*   attr_idx     = (const int*)  d_in[3];
    const float* obs_embs     = (const float*)d_in[4];
    const float* fea_corr     = (const float*)d_in[5];
    const float* W1  = (const float*)d_in[6];
    const float* b1  = (const float*)d_in[7];
    const float* W2  = (const float*)d_in[8];
    const float* b2  = (const float*)d_in[9];
    const float* Wrr = (const float*)d_in[10];
    const float* brr = (const float*)d_in[11];
    const float* Wrc = (const float*)d_in[12];
    const float* brc = (const float*)d_in[13];
    const int E = in_sizes[1];

    int sms = 148;
    cudaDeviceGetAttribute(&sms, cudaDevAttrMultiProcessorCount, 0);

    prep_weights<<<160, 256>>>(W1, W2, Wrr, Wrc);
    attr_rel_mma<<<sms, NTHREADS>>>(
        known_mask, obs_idx, obs_mask_idx, attr_idx, obs_embs, fea_corr,
        b1, b2, brr, brc,
        (float*)d_out, E);
}